// round 12
// baseline (speedup 1.0000x reference)
#include <cuda_runtime.h>
#include <cuda_bf16.h>
#include <cuda_fp16.h>
#include <cstdint>

// Problem constants (fixed by the reference)
#define BB     4
#define NN     10000
#define FIN    64
#define UNITS  64
#define CC     128          // FIN + UNITS
#define EE     160000
#define MROWS  (BB * NN)    // 40000
#define KDIM   384          // MAX_VIEW * CC
#define DEGCAP 64           // bucket capacity (Poisson(16), max ~35)

#define MMA_BF16(acc, a, b0, b1)                                               \
    asm volatile("mma.sync.aligned.m16n8k16.row.col.f32.bf16.bf16.f32 "        \
                 "{%0,%1,%2,%3}, {%4,%5,%6,%7}, {%8,%9}, {%0,%1,%2,%3};"       \
                 : "+f"((acc)[0]), "+f"((acc)[1]), "+f"((acc)[2]), "+f"((acc)[3]) \
                 : "r"((a)[0]), "r"((a)[1]), "r"((a)[2]), "r"((a)[3]),         \
                   "r"(b0), "r"(b1))

// split f32 -> (hi bf16, lo bf16) where lo = bf16(x - float(hi))
__device__ __forceinline__ void bf_split(float x, uint32_t& h, uint32_t& l) {
    __nv_bfloat16 hb = __float2bfloat16(x);
    float res = x - __bfloat162float(hb);
    __nv_bfloat16 lb = __float2bfloat16(res);
    h = (uint32_t)__bfloat16_as_ushort(hb);
    l = (uint32_t)__bfloat16_as_ushort(lb);
}
__device__ __forceinline__ float2 h2f(uint32_t v) {
    __half2 h = *reinterpret_cast<__half2*>(&v);
    return __half22float2(h);
}
__device__ __forceinline__ uint32_t f2h(float x, float y) {
    __half2 h = __float22half2_rn(make_float2(x, y));
    return *reinterpret_cast<uint32_t*>(&h);
}
__device__ __forceinline__ float4 h4f(uint2 v) {
    float2 a = h2f(v.x), b = h2f(v.y);
    return make_float4(a.x, a.y, b.x, b.y);
}
__device__ __forceinline__ void acc4(float4& a, float s, const float4& v) {
    a.x += s * v.x; a.y += s * v.y; a.z += s * v.z; a.w += s * v.w;
}
__device__ __forceinline__ void acc2(float2& a, float s, const float2& v) {
    a.x += s * v.x; a.y += s * v.y;
}

// ---------------- scratch (device globals) ---------------------------------
__device__ int  d_deg[NN];
__device__ int2 d_edges[NN * DEGCAP];   // (src, w-bits)

__device__ uint2 d_xh16 [MROWS * 32];   // packed fp16 [inp|hx]  (128 halves/row)
__device__ uint2 d_y116 [MROWS * 32];   // A  [inp,hx]           (fp16)
__device__ uint2 d_y216 [MROWS * 32];   // A^2[inp,hx]           (fp16)
__device__ uint2 d_rh16 [MROWS * 16];   // r*hx                  (64 halves/row)
__device__ uint2 d_rh116[MROWS * 16];   // A (r*hx)
__device__ uint2 d_rh216[MROWS * 16];   // A^2 (r*hx)
__device__ float d_u    [MROWS * UNITS];// update gate u (fp32)

// transposed weights: [N][K=384] fp32
__device__ float d_wt_ru[128 * KDIM];
__device__ float d_wt_c [64 * KDIM];

// ---------------- bucket CSR build -----------------------------------------
__global__ void k_zero() {
    int i = blockIdx.x * blockDim.x + threadIdx.x;
    if (i < NN) d_deg[i] = 0;
}
__global__ void k_fillb(const int* __restrict__ sidx, const float* __restrict__ ker) {
    int e = blockIdx.x * blockDim.x + threadIdx.x;
    if (e < EE) {
        int dst = sidx[EE + e];
        int pos = atomicAdd(&d_deg[dst], 1);
        if (pos < DEGCAP)
            d_edges[dst * DEGCAP + pos] = make_int2(sidx[e], __float_as_int(ker[e]));
    }
}

// ---------------- fp16 pack of [inp|hx] ------------------------------------
__global__ void k_cvt(const float* __restrict__ inp, const float* __restrict__ hx) {
    int idx = blockIdx.x * blockDim.x + threadIdx.x;   // MROWS*32
    if (idx >= MROWS * 32) return;
    int m = idx >> 5, q = idx & 31;
    const float* p = (q < 16) ? (inp + (size_t)m * 64 + q * 4)
                              : (hx  + (size_t)m * 64 + (q - 16) * 4);
    float4 v = *(const float4*)p;
    d_xh16[idx] = make_uint2(f2h(v.x, v.y), f2h(v.z, v.w));
}

// ---------------- weight transpose -----------------------------------------
__global__ void k_wt(const float* __restrict__ W, float* __restrict__ Wt, int Ncols) {
    int idx = blockIdx.x * blockDim.x + threadIdx.x;
    if (idx < KDIM * Ncols) {
        int k = idx / Ncols, n = idx % Ncols;
        Wt[n * KDIM + k] = W[idx];
    }
}

// ---------------- fp16 graph propagation (gather, unroll 4) ----------------
// 128-half rows: warp b = batch b, lane handles 4 halves (uint2)
__device__ __forceinline__ void prop128h(const uint2* __restrict__ src, uint2* __restrict__ dst) {
    int n = blockIdx.x;
    int b = threadIdx.x >> 5, l = threadIdx.x & 31;
    int deg = min(d_deg[n], DEGCAP);
    const int2* ep = d_edges + n * DEGCAP;
    const uint2* base = src + (size_t)b * NN * 32 + l;
    float4 acc = make_float4(0.f, 0.f, 0.f, 0.f);
    int k = 0;
    for (; k + 3 < deg; k += 4) {
        int2 e0 = ep[k], e1 = ep[k + 1], e2 = ep[k + 2], e3 = ep[k + 3];
        float4 v0 = h4f(base[(size_t)e0.x * 32]);
        float4 v1 = h4f(base[(size_t)e1.x * 32]);
        float4 v2 = h4f(base[(size_t)e2.x * 32]);
        float4 v3 = h4f(base[(size_t)e3.x * 32]);
        acc4(acc, __int_as_float(e0.y), v0); acc4(acc, __int_as_float(e1.y), v1);
        acc4(acc, __int_as_float(e2.y), v2); acc4(acc, __int_as_float(e3.y), v3);
    }
    for (; k < deg; k++) {
        int2 e0 = ep[k];
        float4 v0 = h4f(base[(size_t)e0.x * 32]);
        acc4(acc, __int_as_float(e0.y), v0);
    }
    dst[((size_t)b * NN + n) * 32 + l] = make_uint2(f2h(acc.x, acc.y), f2h(acc.z, acc.w));
}
__global__ void k_prop1h() { prop128h(d_xh16, d_y116); }
__global__ void k_prop2h() { prop128h(d_y116, d_y216); }

// 64-half rows: lane handles 2 halves (one uint)
__device__ __forceinline__ void prop64h(const uint2* __restrict__ src2, uint2* __restrict__ dst2) {
    int n = blockIdx.x;
    int b = threadIdx.x >> 5, l = threadIdx.x & 31;
    int deg = min(d_deg[n], DEGCAP);
    const int2* ep = d_edges + n * DEGCAP;
    const uint32_t* base = (const uint32_t*)src2 + (size_t)b * NN * 32 + l;
    float2 acc = make_float2(0.f, 0.f);
    int k = 0;
    for (; k + 3 < deg; k += 4) {
        int2 e0 = ep[k], e1 = ep[k + 1], e2 = ep[k + 2], e3 = ep[k + 3];
        float2 v0 = h2f(base[(size_t)e0.x * 32]);
        float2 v1 = h2f(base[(size_t)e1.x * 32]);
        float2 v2 = h2f(base[(size_t)e2.x * 32]);
        float2 v3 = h2f(base[(size_t)e3.x * 32]);
        acc2(acc, __int_as_float(e0.y), v0); acc2(acc, __int_as_float(e1.y), v1);
        acc2(acc, __int_as_float(e2.y), v2); acc2(acc, __int_as_float(e3.y), v3);
    }
    for (; k < deg; k++) {
        int2 e0 = ep[k];
        float2 v0 = h2f(base[(size_t)e0.x * 32]);
        acc2(acc, __int_as_float(e0.y), v0);
    }
    ((uint32_t*)dst2)[((size_t)b * NN + n) * 32 + l] = f2h(acc.x, acc.y);
}
__global__ void k_prop3h() { prop64h(d_rh16,  d_rh116); }
__global__ void k_prop4h() { prop64h(d_rh116, d_rh216); }

// ---------------- A-tile element loader (virtual concat) -------------------
// MODE 0 = ru conv: [inp hx y1 y2]; MODE 2 = c conv: [inp rh y1a rh1 y2a rh2]
template <int MODE>
__device__ __forceinline__ float4 load_a4(int c, int gm, int q,
                                          const float* __restrict__ inp,
                                          const float* __restrict__ hx) {
    if (MODE == 0) {
        if (c < 2)  return *(const float4*)(inp + (size_t)gm * 64 + (c & 1) * 32 + q * 4);
        if (c < 4)  return *(const float4*)(hx  + (size_t)gm * 64 + (c & 1) * 32 + q * 4);
        if (c < 8)  return h4f(d_y116[(size_t)gm * 32 + (c - 4) * 8 + q]);
        return h4f(d_y216[(size_t)gm * 32 + (c - 8) * 8 + q]);
    } else {
        if (c < 2)  return *(const float4*)(inp + (size_t)gm * 64 + (c & 1) * 32 + q * 4);
        if (c < 4)  return h4f(d_rh16 [(size_t)gm * 16 + (c & 1) * 8 + q]);
        if (c < 6)  return h4f(d_y116 [(size_t)gm * 32 + (c & 1) * 8 + q]);
        if (c < 8)  return h4f(d_rh116[(size_t)gm * 16 + (c & 1) * 8 + q]);
        if (c < 10) return h4f(d_y216 [(size_t)gm * 32 + (c & 1) * 8 + q]);
        return h4f(d_rh216[(size_t)gm * 16 + (c & 1) * 8 + q]);
    }
}

// ---------------- merged r+u GEMM (BM=128, BN=128, 512 thr) ----------------
// d_rh16 = half(sigmoid(z_r) * hx)  [cols 0..63]
// d_u    = sigmoid(z_u)             [cols 64..127]
__global__ void __launch_bounds__(512)
tc_gemm_ru(const float* __restrict__ inp, const float* __restrict__ hx,
           const float* __restrict__ bias) {
    __shared__ uint32_t As[128][36];   // (ahi | alo<<16)
    __shared__ uint32_t Bs[128][36];   // (bhi | blo<<16)

    const int tid = threadIdx.x;
    const int wid = tid >> 5, lane = tid & 31;
    const int warp_m = wid & 3, warp_n = wid >> 2;     // 4 x 4 warps
    const int gid = lane >> 2, tig = lane & 3;
    const int m0 = blockIdx.x * 128;

    float acc[2][4][4];
#pragma unroll
    for (int i = 0; i < 2; i++)
#pragma unroll
        for (int j = 0; j < 4; j++)
#pragma unroll
            for (int r = 0; r < 4; r++) acc[i][j][r] = 0.f;

    for (int c = 0; c < 12; c++) {
        // A tile: 128 rows x 32 k
#pragma unroll
        for (int i = 0; i < 2; i++) {
            int idx = i * 512 + tid;
            int row = idx >> 3, q = idx & 7;
            int gm = m0 + row;
            float4 v = make_float4(0.f, 0.f, 0.f, 0.f);
            if (gm < MROWS) v = load_a4<0>(c, gm, q, inp, hx);
            uint32_t h0, l0, h1, l1, h2, l2, h3, l3;
            bf_split(v.x, h0, l0); bf_split(v.y, h1, l1);
            bf_split(v.z, h2, l2); bf_split(v.w, h3, l3);
            As[row][q * 4 + 0] = h0 | (l0 << 16);
            As[row][q * 4 + 1] = h1 | (l1 << 16);
            As[row][q * 4 + 2] = h2 | (l2 << 16);
            As[row][q * 4 + 3] = h3 | (l3 << 16);
        }
        // B tile: 128 rows x 32 k
#pragma unroll
        for (int i = 0; i < 2; i++) {
            int idx = i * 512 + tid;
            int row = idx >> 3, q = idx & 7;
            float4 v = *(const float4*)(d_wt_ru + (size_t)row * KDIM + c * 32 + q * 4);
            uint32_t h0, l0, h1, l1, h2, l2, h3, l3;
            bf_split(v.x, h0, l0); bf_split(v.y, h1, l1);
            bf_split(v.z, h2, l2); bf_split(v.w, h3, l3);
            Bs[row][q * 4 + 0] = h0 | (l0 << 16);
            Bs[row][q * 4 + 1] = h1 | (l1 << 16);
            Bs[row][q * 4 + 2] = h2 | (l2 << 16);
            Bs[row][q * 4 + 3] = h3 | (l3 << 16);
        }
        __syncthreads();

        // pass 1+2: (ahi+alo) * bhi over doubled K  (4 k16 steps)
#pragma unroll
        for (int s = 0; s < 4; s++) {
            uint32_t a[2][4];
#pragma unroll
            for (int mi = 0; mi < 2; mi++) {
                int r0 = warp_m * 32 + mi * 16 + gid;
                a[mi][0] = As[r0][s * 8 + tig];
                a[mi][1] = As[r0 + 8][s * 8 + tig];
                a[mi][2] = As[r0][s * 8 + tig + 4];
                a[mi][3] = As[r0 + 8][s * 8 + tig + 4];
            }
#pragma unroll
            for (int nj = 0; nj < 4; nj++) {
                int nr = warp_n * 32 + nj * 8 + gid;
                uint32_t b0 = __byte_perm(Bs[nr][s * 8 + tig], 0, 0x1010);
                uint32_t b1 = __byte_perm(Bs[nr][s * 8 + tig + 4], 0, 0x1010);
                MMA_BF16(acc[0][nj], a[0], b0, b1);
                MMA_BF16(acc[1][nj], a[1], b0, b1);
            }
        }
        // pass 3: ahi * blo over K  (2 k16 steps)
#pragma unroll
        for (int s = 0; s < 2; s++) {
            int j0 = s * 8 + tig, j1 = s * 8 + tig + 4;
            uint32_t a[2][4];
#pragma unroll
            for (int mi = 0; mi < 2; mi++) {
                int r0 = warp_m * 32 + mi * 16 + gid;
                a[mi][0] = __byte_perm(As[r0][2 * j0],     As[r0][2 * j0 + 1],     0x5410);
                a[mi][1] = __byte_perm(As[r0 + 8][2 * j0], As[r0 + 8][2 * j0 + 1], 0x5410);
                a[mi][2] = __byte_perm(As[r0][2 * j1],     As[r0][2 * j1 + 1],     0x5410);
                a[mi][3] = __byte_perm(As[r0 + 8][2 * j1], As[r0 + 8][2 * j1 + 1], 0x5410);
            }
#pragma unroll
            for (int nj = 0; nj < 4; nj++) {
                int nr = warp_n * 32 + nj * 8 + gid;
                uint32_t b0 = __byte_perm(Bs[nr][2 * j0], Bs[nr][2 * j0 + 1], 0x7632);
                uint32_t b1 = __byte_perm(Bs[nr][2 * j1], Bs[nr][2 * j1 + 1], 0x7632);
                MMA_BF16(acc[0][nj], a[0], b0, b1);
                MMA_BF16(acc[1][nj], a[1], b0, b1);
            }
        }
        __syncthreads();
    }

    // ---- epilogue: cols 0..63 -> rh (fp16), cols 64..127 -> u (fp32) ----
#pragma unroll
    for (int mi = 0; mi < 2; mi++) {
#pragma unroll
        for (int nj = 0; nj < 4; nj++) {
            int colL = warp_n * 32 + nj * 8 + 2 * tig;   // 0..127 (even)
            float bv0 = bias[colL], bv1 = bias[colL + 1];
#pragma unroll
            for (int half = 0; half < 2; half++) {
                int m = m0 + warp_m * 32 + mi * 16 + gid + half * 8;
                if (m >= MROWS) continue;
                float v0 = acc[mi][nj][half * 2 + 0] + bv0;
                float v1 = acc[mi][nj][half * 2 + 1] + bv1;
                float s0 = 1.f / (1.f + __expf(-v0));
                float s1 = 1.f / (1.f + __expf(-v1));
                if (colL < 64) {     // r -> rh = r*hx (fp16)
                    float2 h = *(const float2*)(hx + (size_t)m * 64 + colL);
                    ((uint32_t*)d_rh16)[(size_t)m * 32 + (colL >> 1)] = f2h(s0 * h.x, s1 * h.y);
                } else {             // u (fp32)
                    float2 o; o.x = s0; o.y = s1;
                    *(float2*)(d_u + (size_t)m * 64 + colL - 64) = o;
                }
            }
        }
    }
}

// ---------------- c GEMM (BM=128, BN=64, 256 thr) + final gate -------------
__global__ void __launch_bounds__(256)
tc_gemm_c(const float* __restrict__ inp, const float* __restrict__ hx,
          const float* __restrict__ bias, float* __restrict__ out) {
    __shared__ uint32_t As[128][36];
    __shared__ uint32_t Bs[64][36];

    const int tid = threadIdx.x;
    const int wid = tid >> 5, lane = tid & 31;
    const int warp_m = wid & 3, warp_n = wid >> 2;     // 4 x 2 warps
    const int gid = lane >> 2, tig = lane & 3;
    const int m0 = blockIdx.x * 128;

    float acc[2][4][4];
#pragma unroll
    for (int i = 0; i < 2; i++)
#pragma unroll
        for (int j = 0; j < 4; j++)
#pragma unroll
            for (int r = 0; r < 4; r++) acc[i][j][r] = 0.f;

    for (int c = 0; c < 12; c++) {
#pragma unroll
        for (int i = 0; i < 4; i++) {
            int idx = i * 256 + tid;
            int row = idx >> 3, q = idx & 7;
            int gm = m0 + row;
            float4 v = make_float4(0.f, 0.f, 0.f, 0.f);
            if (gm < MROWS) v = load_a4<2>(c, gm, q, inp, hx);
            uint32_t h0, l0, h1, l1, h2, l2, h3, l3;
            bf_split(v.x, h0, l0); bf_split(v.y, h1, l1);
            bf_split(v.z, h2, l2); bf_split(v.w, h3, l3);
            As[row][q * 4 + 0] = h0 | (l0 << 16);
            As[row][q * 4 + 1] = h1 | (l1 << 16);
            As[row][q * 4 + 2] = h2 | (l2 << 16);
            As[row][q * 4 + 3] = h3 | (l3 << 16);
        }
#pragma unroll
        for (int i = 0; i < 2; i++) {
            int idx = i * 256 + tid;
            int row = idx >> 3, q = idx & 7;
            float4 v = *(const float4*)(d_wt_c + (size_t)row * KDIM + c * 32 + q * 4);
            uint32_t h0, l0, h1, l1, h2, l2, h3, l3;
            bf_split(v.x, h0, l0); bf_split(v.y, h1, l1);
            bf_split(v.z, h2, l2); bf_split(v.w, h3, l3);
            Bs[row][q * 4 + 0] = h0 | (l0 << 16);
            Bs[row][q * 4 + 1] = h1 | (l1 << 16);
            Bs[row][q * 4 + 2] = h2 | (l2 << 16);
            Bs[row][q * 4 + 3] = h3 | (l3 << 16);
        }
        __syncthreads();

#pragma unroll
        for (int s = 0; s < 4; s++) {
            uint32_t a[2][4];
#pragma unroll
            for (int mi = 0; mi < 2; mi++) {
                int r0 = warp_m * 32 + mi * 16 + gid;
                a[mi][0] = As[r0][s * 8 + tig];
                a[mi][1] = As[r0 + 8][s * 8 + tig];
                a[mi][2] = As[r0][s * 8 + tig + 4];
                a[mi][3] = As[r0 + 8][s * 8 + tig + 4];
            }
#pragma unroll
            for (int nj = 0; nj < 4; nj++) {
                int nr = warp_n * 32 + nj * 8 + gid;
                uint32_t b0 = __byte_perm(Bs[nr][s * 8 + tig], 0, 0x1010);
                uint32_t b1 = __byte_perm(Bs[nr][s * 8 + tig + 4], 0, 0x1010);
                MMA_BF16(acc[0][nj], a[0], b0, b1);
                MMA_BF16(acc[1][nj], a[1], b0, b1);
            }
        }
#pragma unroll
        for (int s = 0; s < 2; s++) {
            int j0 = s * 8 + tig, j1 = s * 8 + tig + 4;
            uint32_t a[2][4];
#pragma unroll
            for (int mi = 0; mi < 2; mi++) {
                int r0 = warp_m * 32 + mi * 16 + gid;
                a[mi][0] = __byte_perm(As[r0][2 * j0],     As[r0][2 * j0 + 1],     0x5410);
                a[mi][1] = __byte_perm(As[r0 + 8][2 * j0], As[r0 + 8][2 * j0 + 1], 0x5410);
                a[mi][2] = __byte_perm(As[r0][2 * j1],     As[r0][2 * j1 + 1],     0x5410);
                a[mi][3] = __byte_perm(As[r0 + 8][2 * j1], As[r0 + 8][2 * j1 + 1], 0x5410);
            }
#pragma unroll
            for (int nj = 0; nj < 4; nj++) {
                int nr = warp_n * 32 + nj * 8 + gid;
                uint32_t b0 = __byte_perm(Bs[nr][2 * j0], Bs[nr][2 * j0 + 1], 0x7632);
                uint32_t b1 = __byte_perm(Bs[nr][2 * j1], Bs[nr][2 * j1 + 1], 0x7632);
                MMA_BF16(acc[0][nj], a[0], b0, b1);
                MMA_BF16(acc[1][nj], a[1], b0, b1);
            }
        }
        __syncthreads();
    }

    // ---- epilogue: out = u*hx + (1-u)*tanh(.) ----
#pragma unroll
    for (int mi = 0; mi < 2; mi++) {
#pragma unroll
        for (int nj = 0; nj < 4; nj++) {
            int colL = warp_n * 32 + nj * 8 + 2 * tig;   // 0..63 (even)
            float bv0 = bias[colL], bv1 = bias[colL + 1];
#pragma unroll
            for (int half = 0; half < 2; half++) {
                int m = m0 + warp_m * 32 + mi * 16 + gid + half * 8;
                if (m >= MROWS) continue;
                float v0 = acc[mi][nj][half * 2 + 0] + bv0;
                float v1 = acc[mi][nj][half * 2 + 1] + bv1;
                float2 u = *(const float2*)(d_u + (size_t)m * 64 + colL);
                float2 h = *(const float2*)(hx + (size_t)m * 64 + colL);
                float2 o;
                o.x = u.x * h.x + (1.f - u.x) * tanhf(v0);
                o.y = u.y * h.y + (1.f - u.y) * tanhf(v1);
                *(float2*)(out + (size_t)m * 64 + colL) = o;
            }
        }
    }
}

// ---------------- launch ----------------------------------------------------
extern "C" void kernel_launch(void* const* d_in, const int* in_sizes, int n_in,
                              void* d_out, int out_size) {
    const float* inp  = (const float*)d_in[0];
    const float* hx   = (const float*)d_in[1];
    const int*   sidx = (const int*)  d_in[2];
    const float* ker  = (const float*)d_in[3];
    const float* W_ru = (const float*)d_in[4];
    const float* b_ru = (const float*)d_in[5];
    const float* W_c  = (const float*)d_in[6];
    const float* b_c  = (const float*)d_in[7];
    float* out = (float*)d_out;

    float *wt_ru, *wt_c;
    cudaGetSymbolAddress((void**)&wt_ru, d_wt_ru);
    cudaGetSymbolAddress((void**)&wt_c,  d_wt_c);

    const int GRID = (MROWS + 127) / 128;  // 313

    // setup
    k_zero <<<(NN + 255) / 256, 256>>>();
    k_fillb<<<(EE + 255) / 256, 256>>>(sidx, ker);
    k_cvt  <<<(MROWS * 32 + 255) / 256, 256>>>(inp, hx);
    k_wt   <<<(KDIM * 128 + 255) / 256, 256>>>(W_ru, wt_ru, 128);
    k_wt   <<<(KDIM * 64 + 255) / 256, 256>>>(W_c, wt_c, 64);

    // ru conv
    k_prop1h<<<NN, 128>>>();
    k_prop2h<<<NN, 128>>>();
    tc_gemm_ru<<<GRID, 512>>>(inp, hx, b_ru);

    // c conv
    k_prop3h<<<NN, 128>>>();
    k_prop4h<<<NN, 128>>>();
    tc_gemm_c<<<GRID, 256>>>(inp, hx, b_c, out);
}

// round 13
// speedup vs baseline: 1.0646x; 1.0646x over previous
#include <cuda_runtime.h>
#include <cuda_bf16.h>
#include <cstdint>

// Problem constants (fixed by the reference)
#define BB     4
#define NN     10000
#define FIN    64
#define UNITS  64
#define CC     128          // FIN + UNITS
#define EE     160000
#define MROWS  (BB * NN)    // 40000
#define KDIM   384          // MAX_VIEW * CC
#define DEGCAP 64           // bucket capacity (Poisson(16), max ~35)

#define MMA_BF16(acc, a, b0, b1)                                               \
    asm volatile("mma.sync.aligned.m16n8k16.row.col.f32.bf16.bf16.f32 "        \
                 "{%0,%1,%2,%3}, {%4,%5,%6,%7}, {%8,%9}, {%0,%1,%2,%3};"       \
                 : "+f"((acc)[0]), "+f"((acc)[1]), "+f"((acc)[2]), "+f"((acc)[3]) \
                 : "r"((a)[0]), "r"((a)[1]), "r"((a)[2]), "r"((a)[3]),         \
                   "r"(b0), "r"(b1))

// split f32 -> (hi bf16, lo bf16) where lo = bf16(x - float(hi))
__device__ __forceinline__ void bf_split(float x, uint32_t& h, uint32_t& l) {
    __nv_bfloat16 hb = __float2bfloat16(x);
    float res = x - __bfloat162float(hb);
    __nv_bfloat16 lb = __float2bfloat16(res);
    h = (uint32_t)__bfloat16_as_ushort(hb);
    l = (uint32_t)__bfloat16_as_ushort(lb);
}
__device__ __forceinline__ void acc4(float4& a, float s, const float4& v) {
    a.x += s * v.x; a.y += s * v.y; a.z += s * v.z; a.w += s * v.w;
}
__device__ __forceinline__ void acc2(float2& a, float s, const float2& v) {
    a.x += s * v.x; a.y += s * v.y;
}

// ---------------- scratch (device globals) ---------------------------------
__device__ int  d_deg[NN];
__device__ int2 d_edges[NN * DEGCAP];   // (src, w-bits)

__device__ float d_y1[MROWS * CC];
__device__ float d_y2[MROWS * CC];
__device__ float d_u  [MROWS * UNITS];  // update gate u
__device__ float d_rh [MROWS * UNITS];  // r*hx
__device__ float d_rh1[MROWS * UNITS];
__device__ float d_rh2[MROWS * UNITS];

// transposed weights: [N][K=384] fp32
__device__ float d_wt_ru[128 * KDIM];
__device__ float d_wt_c [64 * KDIM];

// ---------------- fused setup: zero deg + both weight transposes -----------
__global__ void k_setup(const float* __restrict__ W_ru, const float* __restrict__ W_c) {
    int idx = blockIdx.x * blockDim.x + threadIdx.x;   // 0 .. KDIM*128-1
    if (idx < NN) d_deg[idx] = 0;
    if (idx < KDIM * 128) {
        int k = idx >> 7, n = idx & 127;
        d_wt_ru[n * KDIM + k] = W_ru[idx];
    }
    if (idx < KDIM * 64) {
        int k = idx >> 6, n = idx & 63;
        d_wt_c[n * KDIM + k] = W_c[idx];
    }
}

__global__ void k_fillb(const int* __restrict__ sidx, const float* __restrict__ ker) {
    int e = blockIdx.x * blockDim.x + threadIdx.x;
    if (e < EE) {
        int dst = sidx[EE + e];
        int pos = atomicAdd(&d_deg[dst], 1);
        if (pos < DEGCAP)
            d_edges[dst * DEGCAP + pos] = make_int2(sidx[e], __float_as_int(ker[e]));
    }
}

// ---------------- graph propagation (unroll 8, 2 nodes/block) --------------
// 128-wide: block = 2 nodes x 4 batch-warps; lane owns a float4 of channels
__device__ __forceinline__ void prop128_body(const float* __restrict__ srcA,
                                             const float* __restrict__ srcB,
                                             float* __restrict__ dst,
                                             int stride) {
    int n = blockIdx.x * 2 + (threadIdx.x >> 7);
    int b = (threadIdx.x >> 5) & 3, l = threadIdx.x & 31;
    int deg = min(d_deg[n], DEGCAP);
    const int2* ep = d_edges + n * DEGCAP;
    // srcB non-null => concat mode: lanes 0-15 from srcA(64w), 16-31 from srcB(64w)
    const float* base;
    if (srcB) base = (l < 16) ? (srcA + (size_t)b * NN * 64 + l * 4)
                              : (srcB + (size_t)b * NN * 64 + (l * 4 - 64));
    else      base = srcA + (size_t)b * NN * 128 + l * 4;
    float4 acc = make_float4(0.f, 0.f, 0.f, 0.f);
    int k = 0;
    for (; k + 7 < deg; k += 8) {
        int2 e0 = ep[k],     e1 = ep[k + 1], e2 = ep[k + 2], e3 = ep[k + 3];
        int2 e4 = ep[k + 4], e5 = ep[k + 5], e6 = ep[k + 6], e7 = ep[k + 7];
        float4 v0 = *(const float4*)(base + (size_t)e0.x * stride);
        float4 v1 = *(const float4*)(base + (size_t)e1.x * stride);
        float4 v2 = *(const float4*)(base + (size_t)e2.x * stride);
        float4 v3 = *(const float4*)(base + (size_t)e3.x * stride);
        float4 v4 = *(const float4*)(base + (size_t)e4.x * stride);
        float4 v5 = *(const float4*)(base + (size_t)e5.x * stride);
        float4 v6 = *(const float4*)(base + (size_t)e6.x * stride);
        float4 v7 = *(const float4*)(base + (size_t)e7.x * stride);
        acc4(acc, __int_as_float(e0.y), v0); acc4(acc, __int_as_float(e1.y), v1);
        acc4(acc, __int_as_float(e2.y), v2); acc4(acc, __int_as_float(e3.y), v3);
        acc4(acc, __int_as_float(e4.y), v4); acc4(acc, __int_as_float(e5.y), v5);
        acc4(acc, __int_as_float(e6.y), v6); acc4(acc, __int_as_float(e7.y), v7);
    }
    for (; k + 3 < deg; k += 4) {
        int2 e0 = ep[k], e1 = ep[k + 1], e2 = ep[k + 2], e3 = ep[k + 3];
        float4 v0 = *(const float4*)(base + (size_t)e0.x * stride);
        float4 v1 = *(const float4*)(base + (size_t)e1.x * stride);
        float4 v2 = *(const float4*)(base + (size_t)e2.x * stride);
        float4 v3 = *(const float4*)(base + (size_t)e3.x * stride);
        acc4(acc, __int_as_float(e0.y), v0); acc4(acc, __int_as_float(e1.y), v1);
        acc4(acc, __int_as_float(e2.y), v2); acc4(acc, __int_as_float(e3.y), v3);
    }
    for (; k < deg; k++) {
        int2 e0 = ep[k];
        float4 v0 = *(const float4*)(base + (size_t)e0.x * stride);
        acc4(acc, __int_as_float(e0.y), v0);
    }
    dst[((size_t)b * NN + n) * 128 + l * 4 + 0] = acc.x;
    dst[((size_t)b * NN + n) * 128 + l * 4 + 1] = acc.y;
    dst[((size_t)b * NN + n) * 128 + l * 4 + 2] = acc.z;
    dst[((size_t)b * NN + n) * 128 + l * 4 + 3] = acc.w;
}
__global__ void k_prop1v(const float* __restrict__ inp, const float* __restrict__ hx) {
    prop128_body(inp, hx, d_y1, 64);
}
__global__ void k_prop2v() { prop128_body(d_y1, nullptr, d_y2, 128); }

// 64-wide: block = 2 nodes x 4 batch-warps; lane owns a float2
__device__ __forceinline__ void prop64_body(const float* __restrict__ x, float* __restrict__ y) {
    int n = blockIdx.x * 2 + (threadIdx.x >> 7);
    int b = (threadIdx.x >> 5) & 3, l = threadIdx.x & 31;
    int deg = min(d_deg[n], DEGCAP);
    const int2* ep = d_edges + n * DEGCAP;
    const float* base = x + (size_t)b * NN * 64 + l * 2;
    float2 acc = make_float2(0.f, 0.f);
    int k = 0;
    for (; k + 7 < deg; k += 8) {
        int2 e0 = ep[k],     e1 = ep[k + 1], e2 = ep[k + 2], e3 = ep[k + 3];
        int2 e4 = ep[k + 4], e5 = ep[k + 5], e6 = ep[k + 6], e7 = ep[k + 7];
        float2 v0 = *(const float2*)(base + (size_t)e0.x * 64);
        float2 v1 = *(const float2*)(base + (size_t)e1.x * 64);
        float2 v2 = *(const float2*)(base + (size_t)e2.x * 64);
        float2 v3 = *(const float2*)(base + (size_t)e3.x * 64);
        float2 v4 = *(const float2*)(base + (size_t)e4.x * 64);
        float2 v5 = *(const float2*)(base + (size_t)e5.x * 64);
        float2 v6 = *(const float2*)(base + (size_t)e6.x * 64);
        float2 v7 = *(const float2*)(base + (size_t)e7.x * 64);
        acc2(acc, __int_as_float(e0.y), v0); acc2(acc, __int_as_float(e1.y), v1);
        acc2(acc, __int_as_float(e2.y), v2); acc2(acc, __int_as_float(e3.y), v3);
        acc2(acc, __int_as_float(e4.y), v4); acc2(acc, __int_as_float(e5.y), v5);
        acc2(acc, __int_as_float(e6.y), v6); acc2(acc, __int_as_float(e7.y), v7);
    }
    for (; k + 3 < deg; k += 4) {
        int2 e0 = ep[k], e1 = ep[k + 1], e2 = ep[k + 2], e3 = ep[k + 3];
        float2 v0 = *(const float2*)(base + (size_t)e0.x * 64);
        float2 v1 = *(const float2*)(base + (size_t)e1.x * 64);
        float2 v2 = *(const float2*)(base + (size_t)e2.x * 64);
        float2 v3 = *(const float2*)(base + (size_t)e3.x * 64);
        acc2(acc, __int_as_float(e0.y), v0); acc2(acc, __int_as_float(e1.y), v1);
        acc2(acc, __int_as_float(e2.y), v2); acc2(acc, __int_as_float(e3.y), v3);
    }
    for (; k < deg; k++) {
        int2 e0 = ep[k];
        float2 v0 = *(const float2*)(base + (size_t)e0.x * 64);
        acc2(acc, __int_as_float(e0.y), v0);
    }
    *(float2*)(y + ((size_t)b * NN + n) * 64 + l * 2) = acc;
}
__global__ void k_prop3v() { prop64_body(d_rh,  d_rh1); }
__global__ void k_prop4v() { prop64_body(d_rh1, d_rh2); }

// ---------------- chunk source resolution (virtual concat) -----------------
template <int MODE>
__device__ __forceinline__ const float* chunk_src(int c, const float* inp, const float* hx,
                                                  int& stride, int& col0) {
    int sub = c & 1;
    if (MODE == 0) {
        switch (c >> 1) {
            case 0:  stride = 64;  col0 = sub * 32;      return inp;
            case 1:  stride = 64;  col0 = sub * 32;      return hx;
            case 2:
            case 3:  stride = 128; col0 = (c - 4) * 32;  return d_y1;
            default: stride = 128; col0 = (c - 8) * 32;  return d_y2;
        }
    } else {
        switch (c >> 1) {
            case 0:  stride = 64;  col0 = sub * 32; return inp;
            case 1:  stride = 64;  col0 = sub * 32; return d_rh;
            case 2:  stride = 128; col0 = sub * 32; return d_y1;
            case 3:  stride = 64;  col0 = sub * 32; return d_rh1;
            case 4:  stride = 128; col0 = sub * 32; return d_y2;
            default: stride = 64;  col0 = sub * 32; return d_rh2;
        }
    }
}

// ---------------- bf16 3-term emulated GEMM + fused epilogue ---------------
// BM=128, BN=64/CTA; 256 thr = 8 warps (4m x 2n); warp tile 32x32.
// MODE 0: blockIdx.y==0 -> d_rh = sigmoid(.)*hx ; ==1 -> d_u = sigmoid(.)
// MODE 1: out = u*hx + (1-u)*tanh(.)
template <int MODE>
__global__ void __launch_bounds__(256)
tc_gemm(const float* __restrict__ inp, const float* __restrict__ hx,
        const float* __restrict__ bias, float* __restrict__ out) {
    __shared__ uint32_t As2[128][36];
    __shared__ uint32_t As3[128][20];
    __shared__ uint32_t Bs2[64][36];
    __shared__ uint32_t Bs3[64][20];

    const int tid = threadIdx.x;
    const int wid = tid >> 5, lane = tid & 31;
    const int warp_m = wid & 3, warp_n = wid >> 2;
    const int gid = lane >> 2, tig = lane & 3;
    const int m0 = blockIdx.x * 128;
    const int n0 = blockIdx.y * 64;

    const float* Wt = (MODE == 0) ? d_wt_ru : d_wt_c;

    float acc[2][4][4];
#pragma unroll
    for (int i = 0; i < 2; i++)
#pragma unroll
        for (int j = 0; j < 4; j++)
#pragma unroll
            for (int r = 0; r < 4; r++) acc[i][j][r] = 0.f;

    for (int c = 0; c < 12; c++) {
        int stride, col0;
        const float* src = chunk_src<MODE>(c, inp, hx, stride, col0);
        // A tile: 128 rows x 32 k
#pragma unroll
        for (int i = 0; i < 4; i++) {
            int idx = i * 256 + tid;
            int row = idx >> 3, q = idx & 7;
            int gm = m0 + row;
            float4 v = make_float4(0.f, 0.f, 0.f, 0.f);
            if (gm < MROWS) v = *(const float4*)(src + (size_t)gm * stride + col0 + q * 4);
            uint32_t h0, l0, h1, l1, h2, l2, h3, l3;
            bf_split(v.x, h0, l0); bf_split(v.y, h1, l1);
            bf_split(v.z, h2, l2); bf_split(v.w, h3, l3);
            As2[row][q * 4 + 0] = h0 | (l0 << 16);
            As2[row][q * 4 + 1] = h1 | (l1 << 16);
            As2[row][q * 4 + 2] = h2 | (l2 << 16);
            As2[row][q * 4 + 3] = h3 | (l3 << 16);
            As3[row][q * 2 + 0] = h0 | (h1 << 16);
            As3[row][q * 2 + 1] = h2 | (h3 << 16);
        }
        // B tile: 64 rows x 32 k
#pragma unroll
        for (int i = 0; i < 2; i++) {
            int idx = i * 256 + tid;
            int row = idx >> 3, q = idx & 7;
            float4 v = *(const float4*)(Wt + (size_t)(n0 + row) * KDIM + c * 32 + q * 4);
            uint32_t h0, l0, h1, l1, h2, l2, h3, l3;
            bf_split(v.x, h0, l0); bf_split(v.y, h1, l1);
            bf_split(v.z, h2, l2); bf_split(v.w, h3, l3);
            Bs2[row][q * 4 + 0] = h0 | (h0 << 16);
            Bs2[row][q * 4 + 1] = h1 | (h1 << 16);
            Bs2[row][q * 4 + 2] = h2 | (h2 << 16);
            Bs2[row][q * 4 + 3] = h3 | (h3 << 16);
            Bs3[row][q * 2 + 0] = l0 | (l1 << 16);
            Bs3[row][q * 2 + 1] = l2 | (l3 << 16);
        }
        __syncthreads();

        // pass 1+2: (ahi+alo)*bhi over K'=64 -> 4 k16 steps
#pragma unroll
        for (int s = 0; s < 4; s++) {
            uint32_t a[2][4];
#pragma unroll
            for (int mi = 0; mi < 2; mi++) {
                int r0 = warp_m * 32 + mi * 16 + gid;
                a[mi][0] = As2[r0][s * 8 + tig];
                a[mi][1] = As2[r0 + 8][s * 8 + tig];
                a[mi][2] = As2[r0][s * 8 + tig + 4];
                a[mi][3] = As2[r0 + 8][s * 8 + tig + 4];
            }
#pragma unroll
            for (int nj = 0; nj < 4; nj++) {
                int nr = warp_n * 32 + nj * 8 + gid;
                uint32_t b0 = Bs2[nr][s * 8 + tig];
                uint32_t b1 = Bs2[nr][s * 8 + tig + 4];
                MMA_BF16(acc[0][nj], a[0], b0, b1);
                MMA_BF16(acc[1][nj], a[1], b0, b1);
            }
        }
        // pass 3: ahi*blo over K=32 -> 2 k16 steps
#pragma unroll
        for (int s = 0; s < 2; s++) {
            uint32_t a[2][4];
#pragma unroll
            for (int mi = 0; mi < 2; mi++) {
                int r0 = warp_m * 32 + mi * 16 + gid;
                a[mi][0] = As3[r0][s * 8 + tig];
                a[mi][1] = As3[r0 + 8][s * 8 + tig];
                a[mi][2] = As3[r0][s * 8 + tig + 4];
                a[mi][3] = As3[r0 + 8][s * 8 + tig + 4];
            }
#pragma unroll
            for (int nj = 0; nj < 4; nj++) {
                int nr = warp_n * 32 + nj * 8 + gid;
                uint32_t b0 = Bs3[nr][s * 8 + tig];
                uint32_t b1 = Bs3[nr][s * 8 + tig + 4];
                MMA_BF16(acc[0][nj], a[0], b0, b1);
                MMA_BF16(acc[1][nj], a[1], b0, b1);
            }
        }
        __syncthreads();
    }

    // ---- epilogue ----
#pragma unroll
    for (int mi = 0; mi < 2; mi++) {
#pragma unroll
        for (int nj = 0; nj < 4; nj++) {
            int colL = warp_n * 32 + nj * 8 + 2 * tig;   // 0..63 (even)
            int col  = n0 + colL;
            float bv0 = bias[col], bv1 = bias[col + 1];
#pragma unroll
            for (int half = 0; half < 2; half++) {
                int m = m0 + warp_m * 32 + mi * 16 + gid + half * 8;
                if (m >= MROWS) continue;
                float v0 = acc[mi][nj][half * 2 + 0] + bv0;
                float v1 = acc[mi][nj][half * 2 + 1] + bv1;
                if (MODE == 0) {
                    float s0 = 1.f / (1.f + __expf(-v0));
                    float s1 = 1.f / (1.f + __expf(-v1));
                    if (n0 == 0) {   // r half -> write r*hx directly
                        float2 h = *(const float2*)(hx + (size_t)m * 64 + colL);
                        float2 o; o.x = s0 * h.x; o.y = s1 * h.y;
                        *(float2*)(d_rh + (size_t)m * 64 + colL) = o;
                    } else {          // u half
                        float2 o; o.x = s0; o.y = s1;
                        *(float2*)(d_u + (size_t)m * 64 + colL) = o;
                    }
                } else {
                    float2 u = *(const float2*)(d_u + (size_t)m * 64 + colL);
                    float2 h = *(const float2*)(hx + (size_t)m * 64 + colL);
                    float2 o;
                    o.x = u.x * h.x + (1.f - u.x) * tanhf(v0);
                    o.y = u.y * h.y + (1.f - u.y) * tanhf(v1);
                    *(float2*)(out + (size_t)m * 64 + colL) = o;
                }
            }
        }
    }
}

// ---------------- launch ----------------------------------------------------
extern "C" void kernel_launch(void* const* d_in, const int* in_sizes, int n_in,
                              void* d_out, int out_size) {
    const float* inp  = (const float*)d_in[0];
    const float* hx   = (const float*)d_in[1];
    const int*   sidx = (const int*)  d_in[2];
    const float* ker  = (const float*)d_in[3];
    const float* W_ru = (const float*)d_in[4];
    const float* b_ru = (const float*)d_in[5];
    const float* W_c  = (const float*)d_in[6];
    const float* b_c  = (const float*)d_in[7];
    float* out = (float*)d_out;

    const int GRID = (MROWS + 127) / 128;  // 313

    // setup: zero deg + both weight transposes in one kernel, then fill
    k_setup<<<(KDIM * 128 + 255) / 256, 256>>>(W_ru, W_c);
    k_fillb<<<(EE + 255) / 256, 256>>>(sidx, ker);

    // ru conv
    k_prop1v<<<NN / 2, 256>>>(inp, hx);
    k_prop2v<<<NN / 2, 256>>>();
    tc_gemm<0><<<dim3(GRID, 2), 256>>>(inp, hx, b_ru, nullptr);

    // c conv (rh produced by GEMM0 epilogue)
    k_prop3v<<<NN / 2, 256>>>();
    k_prop4v<<<NN / 2, 256>>>();
    tc_gemm<1><<<dim3(GRID, 1), 256>>>(inp, hx, b_c, out);
}

// round 16
// speedup vs baseline: 1.1311x; 1.0625x over previous
#include <cuda_runtime.h>
#include <cuda_bf16.h>
#include <cuda_fp16.h>
#include <cstdint>

// Problem constants (fixed by the reference)
#define BB     4
#define NN     10000
#define FIN    64
#define UNITS  64
#define CC     128          // FIN + UNITS
#define EE     160000
#define MROWS  (BB * NN)    // 40000
#define KDIM   384          // MAX_VIEW * CC
#define DEGCAP 64           // bucket capacity (Poisson(16), max ~35)

#define MMA_BF16(acc, a, b0, b1)                                               \
    asm volatile("mma.sync.aligned.m16n8k16.row.col.f32.bf16.bf16.f32 "        \
                 "{%0,%1,%2,%3}, {%4,%5,%6,%7}, {%8,%9}, {%0,%1,%2,%3};"       \
                 : "+f"((acc)[0]), "+f"((acc)[1]), "+f"((acc)[2]), "+f"((acc)[3]) \
                 : "r"((a)[0]), "r"((a)[1]), "r"((a)[2]), "r"((a)[3]),         \
                   "r"(b0), "r"(b1))

// split f32 -> (hi bf16, lo bf16) where lo = bf16(x - float(hi))
__device__ __forceinline__ void bf_split(float x, uint32_t& h, uint32_t& l) {
    __nv_bfloat16 hb = __float2bfloat16(x);
    float res = x - __bfloat162float(hb);
    __nv_bfloat16 lb = __float2bfloat16(res);
    h = (uint32_t)__bfloat16_as_ushort(hb);
    l = (uint32_t)__bfloat16_as_ushort(lb);
}
__device__ __forceinline__ float2 h2f(uint32_t v) {
    __half2 h = *reinterpret_cast<__half2*>(&v);
    return __half22float2(h);
}
__device__ __forceinline__ uint32_t f2h(float x, float y) {
    __half2 h = __float22half2_rn(make_float2(x, y));
    return *reinterpret_cast<uint32_t*>(&h);
}
__device__ __forceinline__ float4 h4f(uint2 v) {
    float2 a = h2f(v.x), b = h2f(v.y);
    return make_float4(a.x, a.y, b.x, b.y);
}
__device__ __forceinline__ void acc4(float4& a, float s, const float4& v) {
    a.x += s * v.x; a.y += s * v.y; a.z += s * v.z; a.w += s * v.w;
}
__device__ __forceinline__ void acc2(float2& a, float s, const float2& v) {
    a.x += s * v.x; a.y += s * v.y;
}

// ---------------- scratch (device globals) ---------------------------------
__device__ int  d_deg[NN];
__device__ int2 d_edges[NN * DEGCAP];   // (src, w-bits)

// fp32 tensors consumed by the GEMMs
__device__ float d_y1[MROWS * CC];
__device__ float d_y2[MROWS * CC];
__device__ float d_u  [MROWS * UNITS];
__device__ float d_rh [MROWS * UNITS];
__device__ float d_rh1[MROWS * UNITS];
__device__ float d_rh2[MROWS * UNITS];

// fp16 mirrors used as gather sources by the props (row = 32/16 uint2)
__device__ uint2 d_xh16 [MROWS * 32];   // [inp|hx]  128 halves/row
__device__ uint2 d_y1h  [MROWS * 32];   // y1        128 halves/row
__device__ uint2 d_rhh  [MROWS * 16];   // rh         64 halves/row
__device__ uint2 d_rh1h [MROWS * 16];   // rh1        64 halves/row

// transposed weights: [N][K=384] fp32
__device__ float d_wt_ru[128 * KDIM];
__device__ float d_wt_c [64 * KDIM];

// ---------------- fused setup: zero deg + weight transposes + fp16 pack ----
__global__ void k_setup(const float* __restrict__ W_ru, const float* __restrict__ W_c,
                        const float* __restrict__ inp, const float* __restrict__ hx) {
    int idx = blockIdx.x * blockDim.x + threadIdx.x;   // 0 .. MROWS*32-1
    if (idx < NN) d_deg[idx] = 0;
    if (idx < KDIM * 128) {
        int k = idx >> 7, n = idx & 127;
        d_wt_ru[n * KDIM + k] = W_ru[idx];
    }
    if (idx < KDIM * 64) {
        int k = idx >> 6, n = idx & 63;
        d_wt_c[n * KDIM + k] = W_c[idx];
    }
    if (idx < MROWS * 32) {
        int m = idx >> 5, q = idx & 31;
        const float* p = (q < 16) ? (inp + (size_t)m * 64 + q * 4)
                                  : (hx  + (size_t)m * 64 + (q - 16) * 4);
        float4 v = *(const float4*)p;
        d_xh16[idx] = make_uint2(f2h(v.x, v.y), f2h(v.z, v.w));
    }
}

__global__ void k_fillb(const int* __restrict__ sidx, const float* __restrict__ ker) {
    int e = blockIdx.x * blockDim.x + threadIdx.x;
    if (e < EE) {
        int dst = sidx[EE + e];
        int pos = atomicAdd(&d_deg[dst], 1);
        if (pos < DEGCAP)
            d_edges[dst * DEGCAP + pos] = make_int2(sidx[e], __float_as_int(ker[e]));
    }
}

// ---------------- props: gather fp16, accumulate fp32, dual-store ----------
// 128-ch: grid NN, block 128 (warp b = batch b); lane owns 4 halves (uint2)
__device__ __forceinline__ void prop128h(const uint2* __restrict__ src,
                                         float* __restrict__ dstF,
                                         uint2* __restrict__ dstH) {
    int n = blockIdx.x;
    int b = threadIdx.x >> 5, l = threadIdx.x & 31;
    int deg = min(d_deg[n], DEGCAP);
    const int2* ep = d_edges + n * DEGCAP;
    const uint2* base = src + (size_t)b * NN * 32 + l;
    float4 acc = make_float4(0.f, 0.f, 0.f, 0.f);
    int k = 0;
    for (; k + 3 < deg; k += 4) {
        int2 e0 = ep[k], e1 = ep[k + 1], e2 = ep[k + 2], e3 = ep[k + 3];
        float4 v0 = h4f(base[(size_t)e0.x * 32]);
        float4 v1 = h4f(base[(size_t)e1.x * 32]);
        float4 v2 = h4f(base[(size_t)e2.x * 32]);
        float4 v3 = h4f(base[(size_t)e3.x * 32]);
        acc4(acc, __int_as_float(e0.y), v0); acc4(acc, __int_as_float(e1.y), v1);
        acc4(acc, __int_as_float(e2.y), v2); acc4(acc, __int_as_float(e3.y), v3);
    }
    for (; k < deg; k++) {
        int2 e0 = ep[k];
        float4 v0 = h4f(base[(size_t)e0.x * 32]);
        acc4(acc, __int_as_float(e0.y), v0);
    }
    size_t row = (size_t)b * NN + n;
    *(float4*)(dstF + row * 128 + l * 4) = acc;
    if (dstH) dstH[row * 32 + l] = make_uint2(f2h(acc.x, acc.y), f2h(acc.z, acc.w));
}
__global__ void k_prop1h() { prop128h(d_xh16, d_y1, d_y1h); }
__global__ void k_prop2h() { prop128h(d_y1h,  d_y2, nullptr); }

// 64-ch: lane owns 2 halves (uint32)
__device__ __forceinline__ void prop64h(const uint2* __restrict__ src2,
                                        float* __restrict__ dstF,
                                        uint2* __restrict__ dstH) {
    int n = blockIdx.x;
    int b = threadIdx.x >> 5, l = threadIdx.x & 31;
    int deg = min(d_deg[n], DEGCAP);
    const int2* ep = d_edges + n * DEGCAP;
    const uint32_t* base = (const uint32_t*)src2 + (size_t)b * NN * 32 + l;
    float2 acc = make_float2(0.f, 0.f);
    int k = 0;
    for (; k + 3 < deg; k += 4) {
        int2 e0 = ep[k], e1 = ep[k + 1], e2 = ep[k + 2], e3 = ep[k + 3];
        float2 v0 = h2f(base[(size_t)e0.x * 32]);
        float2 v1 = h2f(base[(size_t)e1.x * 32]);
        float2 v2 = h2f(base[(size_t)e2.x * 32]);
        float2 v3 = h2f(base[(size_t)e3.x * 32]);
        acc2(acc, __int_as_float(e0.y), v0); acc2(acc, __int_as_float(e1.y), v1);
        acc2(acc, __int_as_float(e2.y), v2); acc2(acc, __int_as_float(e3.y), v3);
    }
    for (; k < deg; k++) {
        int2 e0 = ep[k];
        float2 v0 = h2f(base[(size_t)e0.x * 32]);
        acc2(acc, __int_as_float(e0.y), v0);
    }
    size_t row = (size_t)b * NN + n;
    *(float2*)(dstF + row * 64 + l * 2) = acc;
    if (dstH) ((uint32_t*)dstH)[row * 32 + l] = f2h(acc.x, acc.y);
}
__global__ void k_prop3h() { prop64h(d_rhh,  d_rh1, d_rh1h); }
__global__ void k_prop4h() { prop64h(d_rh1h, d_rh2, nullptr); }

// ---------------- chunk source resolution (virtual concat) -----------------
template <int MODE>
__device__ __forceinline__ const float* chunk_src(int c, const float* inp, const float* hx,
                                                  int& stride, int& col0) {
    int sub = c & 1;
    if (MODE == 0) {
        switch (c >> 1) {
            case 0:  stride = 64;  col0 = sub * 32;      return inp;
            case 1:  stride = 64;  col0 = sub * 32;      return hx;
            case 2:
            case 3:  stride = 128; col0 = (c - 4) * 32;  return d_y1;
            default: stride = 128; col0 = (c - 8) * 32;  return d_y2;
        }
    } else {
        switch (c >> 1) {
            case 0:  stride = 64;  col0 = sub * 32; return inp;
            case 1:  stride = 64;  col0 = sub * 32; return d_rh;
            case 2:  stride = 128; col0 = sub * 32; return d_y1;
            case 3:  stride = 64;  col0 = sub * 32; return d_rh1;
            case 4:  stride = 128; col0 = sub * 32; return d_y2;
            default: stride = 64;  col0 = sub * 32; return d_rh2;
        }
    }
}

// ---------------- bf16 3-term emulated GEMM + fused epilogue ---------------
// BM=128, BN=64/CTA; 256 thr = 8 warps (4m x 2n); warp tile 32x32.
// MODE 0: blockIdx.y==0 -> d_rh/-h = sigmoid(.)*hx ; ==1 -> d_u = sigmoid(.)
// MODE 1: out = u*hx + (1-u)*tanh(.)
template <int MODE>
__global__ void __launch_bounds__(256)
tc_gemm(const float* __restrict__ inp, const float* __restrict__ hx,
        const float* __restrict__ bias, float* __restrict__ out) {
    __shared__ uint32_t As2[128][36];
    __shared__ uint32_t As3[128][20];
    __shared__ uint32_t Bs2[64][36];
    __shared__ uint32_t Bs3[64][20];

    const int tid = threadIdx.x;
    const int wid = tid >> 5, lane = tid & 31;
    const int warp_m = wid & 3, warp_n = wid >> 2;
    const int gid = lane >> 2, tig = lane & 3;
    const int m0 = blockIdx.x * 128;
    const int n0 = blockIdx.y * 64;

    const float* Wt = (MODE == 0) ? d_wt_ru : d_wt_c;

    float acc[2][4][4];
#pragma unroll
    for (int i = 0; i < 2; i++)
#pragma unroll
        for (int j = 0; j < 4; j++)
#pragma unroll
            for (int r = 0; r < 4; r++) acc[i][j][r] = 0.f;

    for (int c = 0; c < 12; c++) {
        int stride, col0;
        const float* src = chunk_src<MODE>(c, inp, hx, stride, col0);
        // A tile: 128 rows x 32 k
#pragma unroll
        for (int i = 0; i < 4; i++) {
            int idx = i * 256 + tid;
            int row = idx >> 3, q = idx & 7;
            int gm = m0 + row;
            float4 v = make_float4(0.f, 0.f, 0.f, 0.f);
            if (gm < MROWS) v = *(const float4*)(src + (size_t)gm * stride + col0 + q * 4);
            uint32_t h0, l0, h1, l1, h2, l2, h3, l3;
            bf_split(v.x, h0, l0); bf_split(v.y, h1, l1);
            bf_split(v.z, h2, l2); bf_split(v.w, h3, l3);
            As2[row][q * 4 + 0] = h0 | (l0 << 16);
            As2[row][q * 4 + 1] = h1 | (l1 << 16);
            As2[row][q * 4 + 2] = h2 | (l2 << 16);
            As2[row][q * 4 + 3] = h3 | (l3 << 16);
            As3[row][q * 2 + 0] = h0 | (h1 << 16);
            As3[row][q * 2 + 1] = h2 | (h3 << 16);
        }
        // B tile: 64 rows x 32 k
#pragma unroll
        for (int i = 0; i < 2; i++) {
            int idx = i * 256 + tid;
            int row = idx >> 3, q = idx & 7;
            float4 v = *(const float4*)(Wt + (size_t)(n0 + row) * KDIM + c * 32 + q * 4);
            uint32_t h0, l0, h1, l1, h2, l2, h3, l3;
            bf_split(v.x, h0, l0); bf_split(v.y, h1, l1);
            bf_split(v.z, h2, l2); bf_split(v.w, h3, l3);
            Bs2[row][q * 4 + 0] = h0 | (h0 << 16);
            Bs2[row][q * 4 + 1] = h1 | (h1 << 16);
            Bs2[row][q * 4 + 2] = h2 | (h2 << 16);
            Bs2[row][q * 4 + 3] = h3 | (h3 << 16);
            Bs3[row][q * 2 + 0] = l0 | (l1 << 16);
            Bs3[row][q * 2 + 1] = l2 | (l3 << 16);
        }
        __syncthreads();

        // pass 1+2: (ahi+alo)*bhi over K'=64 -> 4 k16 steps
#pragma unroll
        for (int s = 0; s < 4; s++) {
            uint32_t a[2][4];
#pragma unroll
            for (int mi = 0; mi < 2; mi++) {
                int r0 = warp_m * 32 + mi * 16 + gid;
                a[mi][0] = As2[r0][s * 8 + tig];
                a[mi][1] = As2[r0 + 8][s * 8 + tig];
                a[mi][2] = As2[r0][s * 8 + tig + 4];
                a[mi][3] = As2[r0 + 8][s * 8 + tig + 4];
            }
#pragma unroll
            for (int nj = 0; nj < 4; nj++) {
                int nr = warp_n * 32 + nj * 8 + gid;
                uint32_t b0 = Bs2[nr][s * 8 + tig];
                uint32_t b1 = Bs2[nr][s * 8 + tig + 4];
                MMA_BF16(acc[0][nj], a[0], b0, b1);
                MMA_BF16(acc[1][nj], a[1], b0, b1);
            }
        }
        // pass 3: ahi*blo over K=32 -> 2 k16 steps
#pragma unroll
        for (int s = 0; s < 2; s++) {
            uint32_t a[2][4];
#pragma unroll
            for (int mi = 0; mi < 2; mi++) {
                int r0 = warp_m * 32 + mi * 16 + gid;
                a[mi][0] = As3[r0][s * 8 + tig];
                a[mi][1] = As3[r0 + 8][s * 8 + tig];
                a[mi][2] = As3[r0][s * 8 + tig + 4];
                a[mi][3] = As3[r0 + 8][s * 8 + tig + 4];
            }
#pragma unroll
            for (int nj = 0; nj < 4; nj++) {
                int nr = warp_n * 32 + nj * 8 + gid;
                uint32_t b0 = Bs3[nr][s * 8 + tig];
                uint32_t b1 = Bs3[nr][s * 8 + tig + 4];
                MMA_BF16(acc[0][nj], a[0], b0, b1);
                MMA_BF16(acc[1][nj], a[1], b0, b1);
            }
        }
        __syncthreads();
    }

    // ---- epilogue ----
#pragma unroll
    for (int mi = 0; mi < 2; mi++) {
#pragma unroll
        for (int nj = 0; nj < 4; nj++) {
            int colL = warp_n * 32 + nj * 8 + 2 * tig;   // 0..63 (even)
            int col  = n0 + colL;
            float bv0 = bias[col], bv1 = bias[col + 1];
#pragma unroll
            for (int half = 0; half < 2; half++) {
                int m = m0 + warp_m * 32 + mi * 16 + gid + half * 8;
                if (m >= MROWS) continue;
                float v0 = acc[mi][nj][half * 2 + 0] + bv0;
                float v1 = acc[mi][nj][half * 2 + 1] + bv1;
                if (MODE == 0) {
                    float s0 = 1.f / (1.f + __expf(-v0));
                    float s1 = 1.f / (1.f + __expf(-v1));
                    if (n0 == 0) {   // r half -> write r*hx (fp32 + fp16 mirror)
                        float2 h = *(const float2*)(hx + (size_t)m * 64 + colL);
                        float2 o; o.x = s0 * h.x; o.y = s1 * h.y;
                        *(float2*)(d_rh + (size_t)m * 64 + colL) = o;
                        ((uint32_t*)d_rhh)[(size_t)m * 32 + (colL >> 1)] = f2h(o.x, o.y);
                    } else {          // u half
                        float2 o; o.x = s0; o.y = s1;
                        *(float2*)(d_u + (size_t)m * 64 + colL) = o;
                    }
                } else {
                    float2 u = *(const float2*)(d_u + (size_t)m * 64 + colL);
                    float2 h = *(const float2*)(hx + (size_t)m * 64 + colL);
                    float2 o;
                    o.x = u.x * h.x + (1.f - u.x) * tanhf(v0);
                    o.y = u.y * h.y + (1.f - u.y) * tanhf(v1);
                    *(float2*)(out + (size_t)m * 64 + colL) = o;
                }
            }
        }
    }
}

// ---------------- launch ----------------------------------------------------
extern "C" void kernel_launch(void* const* d_in, const int* in_sizes, int n_in,
                              void* d_out, int out_size) {
    const float* inp  = (const float*)d_in[0];
    const float* hx   = (const float*)d_in[1];
    const int*   sidx = (const int*)  d_in[2];
    const float* ker  = (const float*)d_in[3];
    const float* W_ru = (const float*)d_in[4];
    const float* b_ru = (const float*)d_in[5];
    const float* W_c  = (const float*)d_in[6];
    const float* b_c  = (const float*)d_in[7];
    float* out = (float*)d_out;

    const int GRID = (MROWS + 127) / 128;  // 313

    // setup: zero deg + weight transposes + fp16 pack of [inp|hx]
    k_setup<<<(MROWS * 32 + 255) / 256, 256>>>(W_ru, W_c, inp, hx);
    k_fillb<<<(EE + 255) / 256, 256>>>(sidx, ker);

    // ru conv
    k_prop1h<<<NN, 128>>>();
    k_prop2h<<<NN, 128>>>();
    tc_gemm<0><<<dim3(GRID, 2), 256>>>(inp, hx, b_ru, nullptr);

    // c conv (rh + fp16 mirror produced by GEMM0 epilogue)
    k_prop3h<<<NN, 128>>>();
    k_prop4h<<<NN, 128>>>();
    tc_gemm<1><<<dim3(GRID, 1), 256>>>(inp, hx, b_c, out);
}

// round 17
// speedup vs baseline: 1.5696x; 1.3877x over previous
#include <cuda_runtime.h>
#include <cuda_fp16.h>
#include <cstdint>

// Problem constants (fixed by the reference)
#define BB     4
#define NN     10000
#define FIN    64
#define UNITS  64
#define CC     128          // FIN + UNITS
#define EE     160000
#define MROWS  (BB * NN)    // 40000
#define KDIM   384          // MAX_VIEW * CC
#define KU32   192          // KDIM halves -> u32 pairs per weight row
#define DEGCAP 64           // bucket capacity (Poisson(16), max ~35)

#define MMA_F16(acc, a, b0, b1)                                                \
    asm volatile("mma.sync.aligned.m16n8k16.row.col.f32.f16.f16.f32 "          \
                 "{%0,%1,%2,%3}, {%4,%5,%6,%7}, {%8,%9}, {%0,%1,%2,%3};"       \
                 : "+f"((acc)[0]), "+f"((acc)[1]), "+f"((acc)[2]), "+f"((acc)[3]) \
                 : "r"((a)[0]), "r"((a)[1]), "r"((a)[2]), "r"((a)[3]),         \
                   "r"(b0), "r"(b1))

__device__ __forceinline__ float2 h2f(uint32_t v) {
    __half2 h = *reinterpret_cast<__half2*>(&v);
    return __half22float2(h);
}
__device__ __forceinline__ uint32_t f2h(float x, float y) {
    __half2 h = __float22half2_rn(make_float2(x, y));
    return *reinterpret_cast<uint32_t*>(&h);
}
__device__ __forceinline__ float4 h4f(uint2 v) {
    float2 a = h2f(v.x), b = h2f(v.y);
    return make_float4(a.x, a.y, b.x, b.y);
}
// fp16 2-term split of a float: x ~= hi + lo
__device__ __forceinline__ void h_split(float x, uint16_t& h, uint16_t& l) {
    __half hh = __float2half_rn(x);
    __half ll = __float2half_rn(x - __half2float(hh));
    h = __half_as_ushort(hh);
    l = __half_as_ushort(ll);
}
__device__ __forceinline__ void acc4(float4& a, float s, const float4& v) {
    a.x += s * v.x; a.y += s * v.y; a.z += s * v.z; a.w += s * v.w;
}
__device__ __forceinline__ void acc2(float2& a, float s, const float2& v) {
    a.x += s * v.x; a.y += s * v.y;
}

// ---------------- scratch (device globals) ---------------------------------
__device__ int  d_deg[NN];
__device__ int2 d_edges[NN * DEGCAP];   // (src, w-bits)

// fp16 tensors (u32 = half2); rows: 64 u32 (128ch) or 32 u32 (64ch)
__device__ uint32_t d_xh16 [MROWS * 64];  // [inp|hx]
__device__ uint32_t d_y1h  [MROWS * 64];  // A  [inp,hx]
__device__ uint32_t d_y2h  [MROWS * 64];  // A^2[inp,hx]
__device__ uint32_t d_rhh  [MROWS * 32];  // r*hx
__device__ uint32_t d_rh1h [MROWS * 32];  // A (r*hx)
__device__ uint32_t d_rh2h [MROWS * 32];  // A^2 (r*hx)
__device__ float    d_u    [MROWS * UNITS];  // update gate (fp32)

// transposed fp16-split weights: [N][KU32] (half2-packed consecutive k)
__device__ uint32_t d_whi_ru[128 * KU32];
__device__ uint32_t d_wlo_ru[128 * KU32];
__device__ uint32_t d_whi_c [64 * KU32];
__device__ uint32_t d_wlo_c [64 * KU32];

// ---------------- fused setup ----------------------------------------------
__global__ void k_setup(const float* __restrict__ W_ru, const float* __restrict__ W_c,
                        const float* __restrict__ inp, const float* __restrict__ hx) {
    int idx = blockIdx.x * blockDim.x + threadIdx.x;   // 0 .. MROWS*32-1
    if (idx < NN) d_deg[idx] = 0;
    // weight split+transpose: W[k][n] -> whi/wlo[n][k/2]
    if (idx < 128 * KU32) {
        int n = idx / KU32, kk = idx % KU32;
        float w0 = W_ru[(2 * kk) * 128 + n];
        float w1 = W_ru[(2 * kk + 1) * 128 + n];
        uint16_t h0, l0, h1, l1;
        h_split(w0, h0, l0); h_split(w1, h1, l1);
        d_whi_ru[idx] = (uint32_t)h0 | ((uint32_t)h1 << 16);
        d_wlo_ru[idx] = (uint32_t)l0 | ((uint32_t)l1 << 16);
    }
    if (idx < 64 * KU32) {
        int n = idx / KU32, kk = idx % KU32;
        float w0 = W_c[(2 * kk) * 64 + n];
        float w1 = W_c[(2 * kk + 1) * 64 + n];
        uint16_t h0, l0, h1, l1;
        h_split(w0, h0, l0); h_split(w1, h1, l1);
        d_whi_c[idx] = (uint32_t)h0 | ((uint32_t)h1 << 16);
        d_wlo_c[idx] = (uint32_t)l0 | ((uint32_t)l1 << 16);
    }
    // fp16 pack of [inp|hx]: 2 u32 per thread
    if (idx < MROWS * 32) {
        int m = idx >> 5, q = idx & 31;
        const float* p = (q < 16) ? (inp + (size_t)m * 64 + q * 4)
                                  : (hx  + (size_t)m * 64 + (q - 16) * 4);
        float4 v = *(const float4*)p;
        d_xh16[idx * 2 + 0] = f2h(v.x, v.y);
        d_xh16[idx * 2 + 1] = f2h(v.z, v.w);
    }
}

__global__ void k_fillb(const int* __restrict__ sidx, const float* __restrict__ ker) {
    int e = blockIdx.x * blockDim.x + threadIdx.x;
    if (e < EE) {
        int dst = sidx[EE + e];
        int pos = atomicAdd(&d_deg[dst], 1);
        if (pos < DEGCAP)
            d_edges[dst * DEGCAP + pos] = make_int2(sidx[e], __float_as_int(ker[e]));
    }
}

// ---------------- props: gather fp16, accumulate fp32, store fp16 ----------
// 128-ch: grid NN, block 128 (warp b = batch b); lane owns 4 halves (uint2)
__device__ __forceinline__ void prop128h(const uint32_t* __restrict__ src,
                                         uint32_t* __restrict__ dst) {
    int n = blockIdx.x;
    int b = threadIdx.x >> 5, l = threadIdx.x & 31;
    int deg = min(d_deg[n], DEGCAP);
    const int2* ep = d_edges + n * DEGCAP;
    const uint2* base = (const uint2*)src + (size_t)b * NN * 32 + l;
    float4 acc = make_float4(0.f, 0.f, 0.f, 0.f);
    int k = 0;
    for (; k + 3 < deg; k += 4) {
        int2 e0 = ep[k], e1 = ep[k + 1], e2 = ep[k + 2], e3 = ep[k + 3];
        float4 v0 = h4f(base[(size_t)e0.x * 32]);
        float4 v1 = h4f(base[(size_t)e1.x * 32]);
        float4 v2 = h4f(base[(size_t)e2.x * 32]);
        float4 v3 = h4f(base[(size_t)e3.x * 32]);
        acc4(acc, __int_as_float(e0.y), v0); acc4(acc, __int_as_float(e1.y), v1);
        acc4(acc, __int_as_float(e2.y), v2); acc4(acc, __int_as_float(e3.y), v3);
    }
    for (; k < deg; k++) {
        int2 e0 = ep[k];
        float4 v0 = h4f(base[(size_t)e0.x * 32]);
        acc4(acc, __int_as_float(e0.y), v0);
    }
    size_t row = (size_t)b * NN + n;
    ((uint2*)dst)[row * 32 + l] = make_uint2(f2h(acc.x, acc.y), f2h(acc.z, acc.w));
}
__global__ void k_prop1h() { prop128h(d_xh16, d_y1h); }
__global__ void k_prop2h() { prop128h(d_y1h,  d_y2h); }

// 64-ch: lane owns 2 halves (uint32)
__device__ __forceinline__ void prop64h(const uint32_t* __restrict__ src,
                                        uint32_t* __restrict__ dst) {
    int n = blockIdx.x;
    int b = threadIdx.x >> 5, l = threadIdx.x & 31;
    int deg = min(d_deg[n], DEGCAP);
    const int2* ep = d_edges + n * DEGCAP;
    const uint32_t* base = src + (size_t)b * NN * 32 + l;
    float2 acc = make_float2(0.f, 0.f);
    int k = 0;
    for (; k + 3 < deg; k += 4) {
        int2 e0 = ep[k], e1 = ep[k + 1], e2 = ep[k + 2], e3 = ep[k + 3];
        float2 v0 = h2f(base[(size_t)e0.x * 32]);
        float2 v1 = h2f(base[(size_t)e1.x * 32]);
        float2 v2 = h2f(base[(size_t)e2.x * 32]);
        float2 v3 = h2f(base[(size_t)e3.x * 32]);
        acc2(acc, __int_as_float(e0.y), v0); acc2(acc, __int_as_float(e1.y), v1);
        acc2(acc, __int_as_float(e2.y), v2); acc2(acc, __int_as_float(e3.y), v3);
    }
    for (; k < deg; k++) {
        int2 e0 = ep[k];
        float2 v0 = h2f(base[(size_t)e0.x * 32]);
        acc2(acc, __int_as_float(e0.y), v0);
    }
    dst[((size_t)b * NN + n) * 32 + l] = f2h(acc.x, acc.y);
}
__global__ void k_prop3h() { prop64h(d_rhh,  d_rh1h); }
__global__ void k_prop4h() { prop64h(d_rh1h, d_rh2h); }

// ---------------- chunk source (all-fp16 virtual concat) -------------------
// returns base ptr, row stride in u32, u32 offset of this 32-half chunk
template <int MODE>
__device__ __forceinline__ const uint32_t* chunk_src(int c, int& rstride, int& coff) {
    if (MODE == 0) {
        if (c < 4)  { rstride = 64; coff = c * 16;       return d_xh16; }
        if (c < 8)  { rstride = 64; coff = (c - 4) * 16; return d_y1h; }
        rstride = 64; coff = (c - 8) * 16; return d_y2h;
    } else {
        if (c < 2)  { rstride = 64; coff = c * 16;        return d_xh16; }
        if (c < 4)  { rstride = 32; coff = (c - 2) * 16;  return d_rhh; }
        if (c < 6)  { rstride = 64; coff = (c - 4) * 16;  return d_y1h; }
        if (c < 8)  { rstride = 32; coff = (c - 6) * 16;  return d_rh1h; }
        if (c < 10) { rstride = 64; coff = (c - 8) * 16;  return d_y2h; }
        rstride = 32; coff = (c - 10) * 16; return d_rh2h;
    }
}

// ---------------- fp16-A / split-B GEMM + fused epilogue -------------------
// BM=128, BN=64/CTA; 256 thr = 8 warps (4m x 2n); warp tile 32x32.
// acc = A_f16 * (Whi + Wlo), fp32 accumulate. 32 MMA/chunk/warp.
// MODE 0: blockIdx.y==0 -> d_rhh = f16(sigmoid(.)*hx); ==1 -> d_u = sigmoid(.)
// MODE 1: out = u*hx + (1-u)*tanh(.)
template <int MODE>
__global__ void __launch_bounds__(256)
tc_gemm(const float* __restrict__ hx, const float* __restrict__ bias,
        float* __restrict__ out) {
    __shared__ uint32_t As [128][20];   // 32 halves (16 u32) + pad
    __shared__ uint32_t Bhi[64][20];
    __shared__ uint32_t Blo[64][20];

    const int tid = threadIdx.x;
    const int wid = tid >> 5, lane = tid & 31;
    const int warp_m = wid & 3, warp_n = wid >> 2;
    const int gid = lane >> 2, tig = lane & 3;
    const int m0 = blockIdx.x * 128;
    const int n0 = blockIdx.y * 64;

    const uint32_t* Whi = (MODE == 0) ? d_whi_ru : d_whi_c;
    const uint32_t* Wlo = (MODE == 0) ? d_wlo_ru : d_wlo_c;

    float acc[2][4][4];
#pragma unroll
    for (int i = 0; i < 2; i++)
#pragma unroll
        for (int j = 0; j < 4; j++)
#pragma unroll
            for (int r = 0; r < 4; r++) acc[i][j][r] = 0.f;

    for (int c = 0; c < 12; c++) {
        int rstride, coff;
        const uint32_t* src = chunk_src<MODE>(c, rstride, coff);
        // A tile: 128 rows x 16 u32  (pure copy, 2 uint4 per thread)
#pragma unroll
        for (int i = 0; i < 2; i++) {
            int idx = i * 256 + tid;          // 0..511 -> uint4 id
            int row = idx >> 2, q = idx & 3;
            uint4 v = *(const uint4*)(src + (size_t)(m0 + row) * rstride + coff + q * 4);
            *(uint4*)&As[row][q * 4] = v;
        }
        // B tiles: 64 rows x 16 u32 each (1 uint4 per thread per array)
        {
            int row = tid >> 2, q = tid & 3;
            size_t off = (size_t)(n0 + row) * KU32 + c * 16 + q * 4;
            *(uint4*)&Bhi[row][q * 4] = *(const uint4*)(Whi + off);
            *(uint4*)&Blo[row][q * 4] = *(const uint4*)(Wlo + off);
        }
        __syncthreads();

#pragma unroll
        for (int s = 0; s < 2; s++) {
            uint32_t a[2][4];
#pragma unroll
            for (int mi = 0; mi < 2; mi++) {
                int r0 = warp_m * 32 + mi * 16 + gid;
                a[mi][0] = As[r0][s * 8 + tig];
                a[mi][1] = As[r0 + 8][s * 8 + tig];
                a[mi][2] = As[r0][s * 8 + tig + 4];
                a[mi][3] = As[r0 + 8][s * 8 + tig + 4];
            }
#pragma unroll
            for (int nj = 0; nj < 4; nj++) {
                int nr = warp_n * 32 + nj * 8 + gid;
                uint32_t bh0 = Bhi[nr][s * 8 + tig];
                uint32_t bh1 = Bhi[nr][s * 8 + tig + 4];
                uint32_t bl0 = Blo[nr][s * 8 + tig];
                uint32_t bl1 = Blo[nr][s * 8 + tig + 4];
                MMA_F16(acc[0][nj], a[0], bh0, bh1);
                MMA_F16(acc[1][nj], a[1], bh0, bh1);
                MMA_F16(acc[0][nj], a[0], bl0, bl1);
                MMA_F16(acc[1][nj], a[1], bl0, bl1);
            }
        }
        __syncthreads();
    }

    // ---- epilogue ----
#pragma unroll
    for (int mi = 0; mi < 2; mi++) {
#pragma unroll
        for (int nj = 0; nj < 4; nj++) {
            int colL = warp_n * 32 + nj * 8 + 2 * tig;   // 0..63 (even)
            int col  = n0 + colL;
            float bv0 = bias[col], bv1 = bias[col + 1];
#pragma unroll
            for (int half = 0; half < 2; half++) {
                int m = m0 + warp_m * 32 + mi * 16 + gid + half * 8;
                if (m >= MROWS) continue;
                float v0 = acc[mi][nj][half * 2 + 0] + bv0;
                float v1 = acc[mi][nj][half * 2 + 1] + bv1;
                if (MODE == 0) {
                    float s0 = 1.f / (1.f + __expf(-v0));
                    float s1 = 1.f / (1.f + __expf(-v1));
                    if (n0 == 0) {   // r half -> rh = r*hx (fp16)
                        float2 h = *(const float2*)(hx + (size_t)m * 64 + colL);
                        d_rhh[(size_t)m * 32 + (colL >> 1)] = f2h(s0 * h.x, s1 * h.y);
                    } else {          // u half (fp32)
                        float2 o; o.x = s0; o.y = s1;
                        *(float2*)(d_u + (size_t)m * 64 + colL) = o;
                    }
                } else {
                    float2 u = *(const float2*)(d_u + (size_t)m * 64 + colL);
                    float2 h = *(const float2*)(hx + (size_t)m * 64 + colL);
                    float2 o;
                    o.x = u.x * h.x + (1.f - u.x) * tanhf(v0);
                    o.y = u.y * h.y + (1.f - u.y) * tanhf(v1);
                    *(float2*)(out + (size_t)m * 64 + colL) = o;
                }
            }
        }
    }
}

// ---------------- launch ----------------------------------------------------
extern "C" void kernel_launch(void* const* d_in, const int* in_sizes, int n_in,
                              void* d_out, int out_size) {
    const float* inp  = (const float*)d_in[0];
    const float* hx   = (const float*)d_in[1];
    const int*   sidx = (const int*)  d_in[2];
    const float* ker  = (const float*)d_in[3];
    const float* W_ru = (const float*)d_in[4];
    const float* b_ru = (const float*)d_in[5];
    const float* W_c  = (const float*)d_in[6];
    const float* b_c  = (const float*)d_in[7];
    float* out = (float*)d_out;

    const int GRID = (MROWS + 127) / 128;  // 313

    // setup: zero deg + fp16-split weight transposes + fp16 pack of [inp|hx]
    k_setup<<<(MROWS * 32 + 255) / 256, 256>>>(W_ru, W_c, inp, hx);
    k_fillb<<<(EE + 255) / 256, 256>>>(sidx, ker);

    // ru conv
    k_prop1h<<<NN, 128>>>();
    k_prop2h<<<NN, 128>>>();
    tc_gemm<0><<<dim3(GRID, 2), 256>>>(hx, b_ru, nullptr);

    // c conv (rh fp16 produced by GEMM0 epilogue)
    k_prop3h<<<NN, 128>>>();
    k_prop4h<<<NN, 128>>>();
    tc_gemm<1><<<dim3(GRID, 1), 256>>>(hx, b_c, out);
}